// round 9
// baseline (speedup 1.0000x reference)
#include <cuda_runtime.h>
#include <cuda_bf16.h>
#include <math.h>

// Problem constants
#define NB     32
#define NPOLY  256
#define VPP    64
#define LDIM   32
#define V_TOT  (1 + NPOLY * VPP)   // 16385 rows per batch in `data`

// Scratch (device globals: no allocations allowed)
__device__ float g_P2[NB * NPOLY * 128];   // agg2 per (b, poly): P = [agg2, agg2]
__device__ float g_Wq[128 * 256];          // folded Wq[:128] + Wq[128:]
__device__ float g_Wk[128 * 256];
__device__ float g_Wv[128 * 256];

// ---- packed f32x2 helpers (sm_103a dual-fp32 pipe; PTX-only) -------------
__device__ __forceinline__ unsigned long long pack2(float x, float y) {
    unsigned long long r;
    asm("mov.b64 %0, {%1, %2};" : "=l"(r) : "f"(x), "f"(y));
    return r;
}
__device__ __forceinline__ unsigned long long ffma2(unsigned long long a,
                                                    unsigned long long b,
                                                    unsigned long long c) {
    unsigned long long d;
    asm("fma.rn.f32x2 %0, %1, %2, %3;" : "=l"(d) : "l"(a), "l"(b), "l"(c));
    return d;
}
__device__ __forceinline__ float2 unpack2(unsigned long long v) {
    float2 f;
    asm("mov.b64 {%0, %1}, %2;" : "=f"(f.x), "=f"(f.y) : "l"(v));
    return f;
}

// ---------------------------------------------------------------------------
// Stage 1: per (b, poly) block — 3 x (GEMM + LayerNorm + ReLU + column max).
// x = concat([h, broadcast(agg)]) => per-row GEMM uses only the top CIN rows
// of W; the agg part folds into a per-block shared term. Only agg2 (128) is
// emitted: P = concat([agg2, agg2]).
//
// Serial-path design (R6, kept):
//  - no smem atomics: per-warp col-max -> wmax[8][128]; warp0 reduces into
//    aggp during the staging phase (one sync).
//  - shared term k-split across 256/COUT threads per column (independent
//    LDGs, short chains); partials summed at accumulator init.
// ---------------------------------------------------------------------------
template<int CIN, int COUT, bool FIRST, bool LAST, int CPREV>
__device__ __forceinline__ void layer(
    const float* __restrict__ in_s,   // 64 x CIN (smem)
    float*       __restrict__ out_s,  // 64 x COUT (smem) or unused if LAST
    float*       __restrict__ Ws,     // smem weight buffer (CIN x COUT floats)
    const float* __restrict__ W,      // global weights ((CIN or 2*CIN) x COUT)
    const float* __restrict__ bias,
    const float* __restrict__ g,
    const float* __restrict__ beta,
    float*       __restrict__ aggp,   // smem: prev agg (CPREV), filled here
    float*       __restrict__ shsP,   // smem: 256 partial shared terms
    float*       __restrict__ wmax,   // smem: 8 x 128 per-warp col maxes
    int tid)
{
    constexpr int PC    = COUT / 32;   // columns per lane (1, 2, or 4)
    constexpr int SPLIT = 256 / COUT;  // threads per column for shared term
    constexpr int KCH   = CIN / SPLIT; // k-chunk per thread
    const int warp = tid >> 5, lane = tid & 31;
    const int rbase = warp * 8;        // this warp's 8 rows

    // Phase A: stage W_top (all threads) + warp0 reduces prev col-max -> aggp
    for (int i = tid; i < CIN * COUT / 4; i += 256)
        ((float4*)Ws)[i] = ((const float4*)W)[i];
    if (!FIRST && warp == 0) {
        #pragma unroll
        for (int c = lane; c < CPREV; c += 32) {
            float m = wmax[c];
            #pragma unroll
            for (int w = 1; w < 8; w++) m = fmaxf(m, wmax[w * 128 + c]);
            aggp[c] = m;
        }
    }
    __syncthreads();

    // Phase B: shared-term partials (k-split; all 256 threads busy)
    {
        const int c    = tid & (COUT - 1);
        const int part = tid >> (31 - __clz(COUT));   // tid / COUT
        float s = (part == 0) ? bias[c] : 0.f;
        if (!FIRST) {
            const float* wb = W + (size_t)(CIN + part * KCH) * COUT + c;
            const float* ap = aggp + part * KCH;
            #pragma unroll 8
            for (int kk = 0; kk < KCH; kk++)
                s = fmaf(ap[kk], wb[(size_t)kk * COUT], s);
        }
        shsP[part * COUT + c] = s;
    }
    __syncthreads();

    // Accumulator init = sum of SPLIT partials for this lane's columns
    float s0[PC];
    #pragma unroll
    for (int j = 0; j < PC; j++) {
        const int c = lane * PC + j;
        float t = shsP[c];
        #pragma unroll
        for (int part = 1; part < SPLIT; part++) t += shsP[part * COUT + c];
        s0[j] = t;
    }

    float gr[PC], br[PC], mx[PC];
    #pragma unroll
    for (int j = 0; j < PC; j++) {
        const int c = lane * PC + j;
        gr[j] = g[c]; br[j] = beta[c]; mx[j] = 0.f;
    }

    float vals[8][PC];   // post-GEMM values

    if constexpr (PC == 4) {
        unsigned long long acc[8][2];
        {
            const unsigned long long i0 = pack2(s0[0], s0[1]);
            const unsigned long long i1 = pack2(s0[2], s0[3]);
            #pragma unroll
            for (int r = 0; r < 8; r++) { acc[r][0] = i0; acc[r][1] = i1; }
        }
        for (int k0 = 0; k0 < CIN; k0 += 4) {
            unsigned long long w[4][2];
            #pragma unroll
            for (int kk = 0; kk < 4; kk++) {
                const ulonglong2 wv =
                    *(const ulonglong2*)(Ws + (k0 + kk) * COUT + lane * 4);
                w[kk][0] = wv.x; w[kk][1] = wv.y;
            }
            #pragma unroll
            for (int r = 0; r < 8; r++) {
                const float4 a = *(const float4*)(in_s + (rbase + r) * CIN + k0);
                unsigned long long ap;
                ap = pack2(a.x, a.x);
                acc[r][0] = ffma2(ap, w[0][0], acc[r][0]);
                acc[r][1] = ffma2(ap, w[0][1], acc[r][1]);
                ap = pack2(a.y, a.y);
                acc[r][0] = ffma2(ap, w[1][0], acc[r][0]);
                acc[r][1] = ffma2(ap, w[1][1], acc[r][1]);
                ap = pack2(a.z, a.z);
                acc[r][0] = ffma2(ap, w[2][0], acc[r][0]);
                acc[r][1] = ffma2(ap, w[2][1], acc[r][1]);
                ap = pack2(a.w, a.w);
                acc[r][0] = ffma2(ap, w[3][0], acc[r][0]);
                acc[r][1] = ffma2(ap, w[3][1], acc[r][1]);
            }
        }
        #pragma unroll
        for (int r = 0; r < 8; r++) {
            const float2 f0 = unpack2(acc[r][0]), f1 = unpack2(acc[r][1]);
            vals[r][0] = f0.x; vals[r][1] = f0.y; vals[r][2] = f1.x; vals[r][3] = f1.y;
        }
    } else if constexpr (PC == 2) {
        unsigned long long acc[8];
        {
            const unsigned long long i0 = pack2(s0[0], s0[1]);
            #pragma unroll
            for (int r = 0; r < 8; r++) acc[r] = i0;
        }
        for (int k0 = 0; k0 < CIN; k0 += 4) {
            unsigned long long w[4];
            #pragma unroll
            for (int kk = 0; kk < 4; kk++)
                w[kk] = *(const unsigned long long*)(Ws + (k0 + kk) * COUT + lane * 2);
            #pragma unroll
            for (int r = 0; r < 8; r++) {
                const float4 a = *(const float4*)(in_s + (rbase + r) * CIN + k0);
                acc[r] = ffma2(pack2(a.x, a.x), w[0], acc[r]);
                acc[r] = ffma2(pack2(a.y, a.y), w[1], acc[r]);
                acc[r] = ffma2(pack2(a.z, a.z), w[2], acc[r]);
                acc[r] = ffma2(pack2(a.w, a.w), w[3], acc[r]);
            }
        }
        #pragma unroll
        for (int r = 0; r < 8; r++) {
            const float2 f = unpack2(acc[r]);
            vals[r][0] = f.x; vals[r][1] = f.y;
        }
    } else {
        float acc[8];
        #pragma unroll
        for (int r = 0; r < 8; r++) acc[r] = s0[0];
        for (int k0 = 0; k0 < CIN; k0 += 4) {
            float w[4];
            #pragma unroll
            for (int kk = 0; kk < 4; kk++)
                w[kk] = Ws[(k0 + kk) * COUT + lane];
            #pragma unroll
            for (int r = 0; r < 8; r++) {
                const float4 a = *(const float4*)(in_s + (rbase + r) * CIN + k0);
                acc[r] = fmaf(a.x, w[0], acc[r]);
                acc[r] = fmaf(a.y, w[1], acc[r]);
                acc[r] = fmaf(a.z, w[2], acc[r]);
                acc[r] = fmaf(a.w, w[3], acc[r]);
            }
        }
        #pragma unroll
        for (int r = 0; r < 8; r++) vals[r][0] = acc[r];
    }

    // Per-row LayerNorm + ReLU + running column max
    #pragma unroll
    for (int r = 0; r < 8; r++) {
        float sum = 0.f, sq = 0.f;
        #pragma unroll
        for (int j = 0; j < PC; j++) { sum += vals[r][j]; sq += vals[r][j] * vals[r][j]; }
        #pragma unroll
        for (int o = 16; o > 0; o >>= 1) {
            sum += __shfl_xor_sync(0xffffffffu, sum, o);
            sq  += __shfl_xor_sync(0xffffffffu, sq,  o);
        }
        const float mu  = sum * (1.0f / COUT);
        const float var = fmaxf(sq * (1.0f / COUT) - mu * mu, 0.f);
        const float inv = rsqrtf(var + 1e-5f);
        float v[PC];
        #pragma unroll
        for (int j = 0; j < PC; j++) {
            v[j] = fmaxf(fmaf(gr[j] * (vals[r][j] - mu), inv, br[j]), 0.f);
            mx[j] = fmaxf(mx[j], v[j]);
        }
        if (!LAST) {
            if constexpr (PC == 4)
                *(float4*)(out_s + (rbase + r) * COUT + lane * 4) =
                    make_float4(v[0], v[1], v[2], v[3]);
            else if constexpr (PC == 2)
                *(float2*)(out_s + (rbase + r) * COUT + lane * 2) =
                    make_float2(v[0], v[1]);
            else
                out_s[(rbase + r) * COUT + lane] = v[0];
        }
    }
    // Per-warp column max -> wmax[warp][*] (no atomics; each warp owns a row)
    if constexpr (PC == 4)
        *(float4*)(wmax + warp * 128 + lane * 4) = make_float4(mx[0], mx[1], mx[2], mx[3]);
    else if constexpr (PC == 2)
        *(float2*)(wmax + warp * 128 + lane * 2) = make_float2(mx[0], mx[1]);
    else
        wmax[warp * 128 + lane] = mx[0];
    __syncthreads();
}

__global__ void __launch_bounds__(256, 3) stage1_kernel(
    const float* __restrict__ data,
    const float* __restrict__ W0, const float* __restrict__ b0,
    const float* __restrict__ g0, const float* __restrict__ be0,
    const float* __restrict__ W1, const float* __restrict__ b1,
    const float* __restrict__ g1, const float* __restrict__ be1,
    const float* __restrict__ W2, const float* __restrict__ b2,
    const float* __restrict__ g2, const float* __restrict__ be2)
{
    extern __shared__ float smem[];
    // Layout (13696 floats = 53.5 KB; 3 CTAs/SM fit in 228 KB):
    float* bufA = smem;                  // 64*64 (x 64x32, later h1 64x64)
    float* Ws   = bufA + 64 * 64;        // 64*128 weight tile
    float* bufB = Ws + 4096;             // h0 (64x32) aliases Ws[4096..6143]:
                                         // layer1 stages Ws[0..1023], layer2
                                         // Ws[0..2047]; layer3 staging clobbers
                                         // only after h0 is dead (sync-fenced).
    float* wmax = Ws + 64 * 128;         // 8*128 per-warp col maxes
    float* aggp = wmax + 8 * 128;        // 128
    float* shsP = aggp + 128;            // 256 partial shared terms

    const int tid = threadIdx.x;
    const int blk = blockIdx.x;          // b*NPOLY + p
    const int b = blk >> 8, p = blk & 255;

    // Load x tile (64 x 32), zero channel 31 (vecs[:, :, -1] = 0)
    const float* src = data + (size_t)b * V_TOT * LDIM + LDIM + (size_t)p * VPP * LDIM;
    for (int i = tid; i < 64 * 32; i += 256) {
        float v = src[i];
        if ((i & 31) == 31) v = 0.f;
        bufA[i] = v;
    }
    __syncthreads();

    layer<32, 32,  true,  false, 32>(bufA, bufB, Ws, W0, b0, g0, be0, aggp, shsP, wmax, tid);
    layer<32, 64,  false, false, 32>(bufB, bufA, Ws, W1, b1, g1, be1, aggp, shsP, wmax, tid);
    layer<64, 128, false, true,  64>(bufA, nullptr, Ws, W2, b2, g2, be2, aggp, shsP, wmax, tid);

    // Final reduction of layer-3 per-warp maxes -> P2
    if (tid < 128) {
        float m = wmax[tid];
        #pragma unroll
        for (int w = 1; w < 8; w++) m = fmaxf(m, wmax[w * 128 + tid]);
        g_P2[(size_t)blk * 128 + tid] = m;
    }
}

// ---------------------------------------------------------------------------
// Fold Wq/Wk/Wv:  W_eff[j][c] = W[j][c] + W[j+128][c]   (P = [agg2, agg2]).
// Runs with high parallelism; leaves folded weights hot in L2 for attn.
// ---------------------------------------------------------------------------
__global__ void __launch_bounds__(256) fold_kernel(
    const float* __restrict__ Wq, const float* __restrict__ Wk,
    const float* __restrict__ Wv)
{
    const int i = blockIdx.x * 256 + threadIdx.x;
    if (i >= 128 * 256) return;
    const int j = i >> 8, c = i & 255;
    g_Wq[i] = Wq[j * 256 + c] + Wq[(j + 128) * 256 + c];
    g_Wk[i] = Wk[j * 256 + c] + Wk[(j + 128) * 256 + c];
    g_Wv[i] = Wv[j * 256 + c] + Wv[(j + 128) * 256 + c];
}

// ---------------------------------------------------------------------------
// Stage 2: attention, algebraically reduced. One block per batch.
//   q = P2[b, aid] @ Wq_eff + bq
//   t = Wk_eff @ q            (scores = P2 . t / 16 + const; const cancels)
//   att = softmax(scores)
//   out = (sum_p att_p * P2[b,p]) @ Wv_eff + bv
// ---------------------------------------------------------------------------
__global__ void __launch_bounds__(256) attn_kernel(
    const float* __restrict__ data,
    const float* __restrict__ bq, const float* __restrict__ bv,
    float* __restrict__ out)
{
    __shared__ float ps[128], qs[256], ts[128], att[256], pbar[128], red[256];
    const int b = blockIdx.x, tid = threadIdx.x;

    const int aid = (int)data[(size_t)b * V_TOT * LDIM];   // data[b][0][0]
    if (tid < 128) ps[tid] = g_P2[((size_t)b * NPOLY + aid) * 128 + tid];
    __syncthreads();

    // q[c] (unroll 8 => 8 outstanding LDGs vs L2 latency)
    {
        float acc = bq[tid];
        #pragma unroll 8
        for (int j = 0; j < 128; j++) acc = fmaf(ps[j], g_Wq[j * 256 + tid], acc);
        qs[tid] = acc;
    }
    __syncthreads();

    // t[j] = sum_c Wk_eff[j][c] * q[c]
    if (tid < 128) {
        float acc = 0.f;
        #pragma unroll 8
        for (int c = 0; c < 256; c++) acc = fmaf(g_Wk[tid * 256 + c], qs[c], acc);
        ts[tid] = acc;
    }
    __syncthreads();

    // scores (per poly p = tid)
    float s = 0.f;
    {
        const float4* Pp = (const float4*)(g_P2 + ((size_t)b * NPOLY + tid) * 128);
        #pragma unroll 8
        for (int j = 0; j < 32; j++) {
            float4 pv = Pp[j];
            s = fmaf(pv.x, ts[4 * j + 0], s);
            s = fmaf(pv.y, ts[4 * j + 1], s);
            s = fmaf(pv.z, ts[4 * j + 2], s);
            s = fmaf(pv.w, ts[4 * j + 3], s);
        }
        s *= 0.0625f;   // 1/sqrt(256)
    }
    // softmax over 256
    red[tid] = s; __syncthreads();
    for (int o = 128; o > 0; o >>= 1) {
        if (tid < o) red[tid] = fmaxf(red[tid], red[tid + o]);
        __syncthreads();
    }
    const float m = red[0]; __syncthreads();
    const float e = expf(s - m);
    red[tid] = e; __syncthreads();
    for (int o = 128; o > 0; o >>= 1) {
        if (tid < o) red[tid] += red[tid + o];
        __syncthreads();
    }
    att[tid] = e / red[0];
    __syncthreads();

    // pbar[j] = sum_p att[p] * P2[b,p,j]   (coalesced across tid=j)
    if (tid < 128) {
        float acc = 0.f;
        const float* Pb = g_P2 + (size_t)b * NPOLY * 128;
        #pragma unroll 8
        for (int p = 0; p < 256; p++) acc = fmaf(att[p], Pb[p * 128 + tid], acc);
        pbar[tid] = acc;
    }
    __syncthreads();

    // out[c]
    {
        float acc = bv[tid];
        #pragma unroll 8
        for (int j = 0; j < 128; j++) acc = fmaf(pbar[j], g_Wv[j * 256 + tid], acc);
        out[b * 256 + tid] = acc;
    }
}

// ---------------------------------------------------------------------------
extern "C" void kernel_launch(void* const* d_in, const int* in_sizes, int n_in,
                              void* d_out, int out_size)
{
    const float* data = (const float*)d_in[0];
    const float* W0 = (const float*)d_in[1];
    const float* b0 = (const float*)d_in[2];
    const float* g0 = (const float*)d_in[3];
    const float* be0= (const float*)d_in[4];
    const float* W1 = (const float*)d_in[5];
    const float* b1 = (const float*)d_in[6];
    const float* g1 = (const float*)d_in[7];
    const float* be1= (const float*)d_in[8];
    const float* W2 = (const float*)d_in[9];
    const float* b2 = (const float*)d_in[10];
    const float* g2 = (const float*)d_in[11];
    const float* be2= (const float*)d_in[12];
    const float* Wq = (const float*)d_in[13];
    const float* bq = (const float*)d_in[14];
    const float* Wk = (const float*)d_in[15];
    const float* bk = (const float*)d_in[16];
    const float* Wv = (const float*)d_in[17];
    const float* bv = (const float*)d_in[18];
    float* out = (float*)d_out;
    (void)bk;

    const int smem_bytes = (64*64 + 64*128 + 8*128 + 128 + 256) * (int)sizeof(float);
    cudaFuncSetAttribute(stage1_kernel,
                         cudaFuncAttributeMaxDynamicSharedMemorySize, smem_bytes);

    stage1_kernel<<<NB * NPOLY, 256, smem_bytes>>>(
        data, W0, b0, g0, be0, W1, b1, g1, be1, W2, b2, g2, be2);
    fold_kernel<<<(128 * 256 + 255) / 256, 256>>>(Wq, Wk, Wv);
    attn_kernel<<<NB, 256>>>(data, bq, bv, out);
}

// round 11
// speedup vs baseline: 1.6225x; 1.6225x over previous
#include <cuda_runtime.h>
#include <cuda_bf16.h>
#include <math.h>

// Problem constants
#define NB     32
#define NPOLY  256
#define VPP    64
#define LDIM   32
#define V_TOT  (1 + NPOLY * VPP)   // 16385 rows per batch in `data`

// Scratch (device globals: no allocations allowed)
__device__ float g_P2[NB * NPOLY * 128];   // agg2 per (b, poly): P = [agg2, agg2]
__device__ float g_Wq[128 * 256];          // folded Wq[:128] + Wq[128:]
__device__ float g_Wk[128 * 256];
__device__ float g_Wv[128 * 256];

// ---- packed f32x2 helpers (sm_103a dual-fp32 pipe; PTX-only) -------------
__device__ __forceinline__ unsigned long long pack2(float x, float y) {
    unsigned long long r;
    asm("mov.b64 %0, {%1, %2};" : "=l"(r) : "f"(x), "f"(y));
    return r;
}
__device__ __forceinline__ unsigned long long ffma2(unsigned long long a,
                                                    unsigned long long b,
                                                    unsigned long long c) {
    unsigned long long d;
    asm("fma.rn.f32x2 %0, %1, %2, %3;" : "=l"(d) : "l"(a), "l"(b), "l"(c));
    return d;
}
__device__ __forceinline__ float2 unpack2(unsigned long long v) {
    float2 f;
    asm("mov.b64 {%0, %1}, %2;" : "=f"(f.x), "=f"(f.y) : "l"(v));
    return f;
}

// ---------------------------------------------------------------------------
// Stage 1 layer: GEMM + LayerNorm + ReLU + per-warp column max.
// Weights (top CIN rows) are PRE-STAGED in smem (Ws) at kernel start.
// x = concat([h, broadcast(agg)]) => agg part folds into a per-block shared
// term computed k-split from global W bottom rows.
// ---------------------------------------------------------------------------
template<int CIN, int COUT, bool FIRST, bool LAST, int CPREV>
__device__ __forceinline__ void layer(
    const float* __restrict__ in_s,   // 64 x CIN (smem)
    float*       __restrict__ out_s,  // 64 x COUT (smem) or unused if LAST
    const float* __restrict__ Ws,     // smem: pre-staged W[0:CIN][0:COUT]
    const float* __restrict__ W,      // global weights ((CIN or 2*CIN) x COUT)
    const float* __restrict__ bias,
    const float* __restrict__ g,
    const float* __restrict__ beta,
    float*       __restrict__ aggp,   // smem: prev agg (CPREV)
    float*       __restrict__ shsP,   // smem: 256 partial shared terms
    float*       __restrict__ wmax,   // smem: 8 x 128 per-warp col maxes
    int tid)
{
    constexpr int PC    = COUT / 32;   // columns per lane (1, 2, or 4)
    constexpr int SPLIT = 256 / COUT;  // threads per column for shared term
    constexpr int KCH   = CIN / SPLIT; // k-chunk per thread
    const int warp = tid >> 5, lane = tid & 31;
    const int rbase = warp * 8;        // this warp's 8 rows

    float s0[PC];                      // accumulator init (shared term)

    if constexpr (FIRST) {
        // bias only — no agg, no partials, no extra syncs
        #pragma unroll
        for (int j = 0; j < PC; j++) s0[j] = bias[lane * PC + j];
    } else {
        // Reduce prev per-warp col maxes -> aggp (CPREV threads, 8-deep)
        if (tid < CPREV) {
            float m = wmax[tid];
            #pragma unroll
            for (int w = 1; w < 8; w++) m = fmaxf(m, wmax[w * 128 + tid]);
            aggp[tid] = m;
        }
        __syncthreads();

        // Shared-term partials (k-split; all 256 threads busy)
        {
            const int c    = tid & (COUT - 1);
            const int part = tid >> (31 - __clz(COUT));   // tid / COUT
            float s = (part == 0) ? bias[c] : 0.f;
            const float* wb = W + (size_t)(CIN + part * KCH) * COUT + c;
            const float* ap = aggp + part * KCH;
            #pragma unroll 8
            for (int kk = 0; kk < KCH; kk++)
                s = fmaf(ap[kk], wb[(size_t)kk * COUT], s);
            shsP[part * COUT + c] = s;
        }
        __syncthreads();

        #pragma unroll
        for (int j = 0; j < PC; j++) {
            const int c = lane * PC + j;
            float t = shsP[c];
            #pragma unroll
            for (int part = 1; part < SPLIT; part++) t += shsP[part * COUT + c];
            s0[j] = t;
        }
    }

    float gr[PC], br[PC], mx[PC];
    #pragma unroll
    for (int j = 0; j < PC; j++) {
        const int c = lane * PC + j;
        gr[j] = g[c]; br[j] = beta[c]; mx[j] = 0.f;
    }

    float vals[8][PC];   // post-GEMM values

    if constexpr (PC == 4) {
        unsigned long long acc[8][2];
        {
            const unsigned long long i0 = pack2(s0[0], s0[1]);
            const unsigned long long i1 = pack2(s0[2], s0[3]);
            #pragma unroll
            for (int r = 0; r < 8; r++) { acc[r][0] = i0; acc[r][1] = i1; }
        }
        for (int k0 = 0; k0 < CIN; k0 += 4) {
            unsigned long long w[4][2];
            #pragma unroll
            for (int kk = 0; kk < 4; kk++) {
                const ulonglong2 wv =
                    *(const ulonglong2*)(Ws + (k0 + kk) * COUT + lane * 4);
                w[kk][0] = wv.x; w[kk][1] = wv.y;
            }
            #pragma unroll
            for (int r = 0; r < 8; r++) {
                const float4 a = *(const float4*)(in_s + (rbase + r) * CIN + k0);
                unsigned long long ap;
                ap = pack2(a.x, a.x);
                acc[r][0] = ffma2(ap, w[0][0], acc[r][0]);
                acc[r][1] = ffma2(ap, w[0][1], acc[r][1]);
                ap = pack2(a.y, a.y);
                acc[r][0] = ffma2(ap, w[1][0], acc[r][0]);
                acc[r][1] = ffma2(ap, w[1][1], acc[r][1]);
                ap = pack2(a.z, a.z);
                acc[r][0] = ffma2(ap, w[2][0], acc[r][0]);
                acc[r][1] = ffma2(ap, w[2][1], acc[r][1]);
                ap = pack2(a.w, a.w);
                acc[r][0] = ffma2(ap, w[3][0], acc[r][0]);
                acc[r][1] = ffma2(ap, w[3][1], acc[r][1]);
            }
        }
        #pragma unroll
        for (int r = 0; r < 8; r++) {
            const float2 f0 = unpack2(acc[r][0]), f1 = unpack2(acc[r][1]);
            vals[r][0] = f0.x; vals[r][1] = f0.y; vals[r][2] = f1.x; vals[r][3] = f1.y;
        }
    } else if constexpr (PC == 2) {
        unsigned long long acc[8];
        {
            const unsigned long long i0 = pack2(s0[0], s0[1]);
            #pragma unroll
            for (int r = 0; r < 8; r++) acc[r] = i0;
        }
        for (int k0 = 0; k0 < CIN; k0 += 4) {
            unsigned long long w[4];
            #pragma unroll
            for (int kk = 0; kk < 4; kk++)
                w[kk] = *(const unsigned long long*)(Ws + (k0 + kk) * COUT + lane * 2);
            #pragma unroll
            for (int r = 0; r < 8; r++) {
                const float4 a = *(const float4*)(in_s + (rbase + r) * CIN + k0);
                acc[r] = ffma2(pack2(a.x, a.x), w[0], acc[r]);
                acc[r] = ffma2(pack2(a.y, a.y), w[1], acc[r]);
                acc[r] = ffma2(pack2(a.z, a.z), w[2], acc[r]);
                acc[r] = ffma2(pack2(a.w, a.w), w[3], acc[r]);
            }
        }
        #pragma unroll
        for (int r = 0; r < 8; r++) {
            const float2 f = unpack2(acc[r]);
            vals[r][0] = f.x; vals[r][1] = f.y;
        }
    } else {
        float acc[8];
        #pragma unroll
        for (int r = 0; r < 8; r++) acc[r] = s0[0];
        for (int k0 = 0; k0 < CIN; k0 += 4) {
            float w[4];
            #pragma unroll
            for (int kk = 0; kk < 4; kk++)
                w[kk] = Ws[(k0 + kk) * COUT + lane];
            #pragma unroll
            for (int r = 0; r < 8; r++) {
                const float4 a = *(const float4*)(in_s + (rbase + r) * CIN + k0);
                acc[r] = fmaf(a.x, w[0], acc[r]);
                acc[r] = fmaf(a.y, w[1], acc[r]);
                acc[r] = fmaf(a.z, w[2], acc[r]);
                acc[r] = fmaf(a.w, w[3], acc[r]);
            }
        }
        #pragma unroll
        for (int r = 0; r < 8; r++) vals[r][0] = acc[r];
    }

    // Per-row LayerNorm + ReLU + running column max
    #pragma unroll
    for (int r = 0; r < 8; r++) {
        float sum = 0.f, sq = 0.f;
        #pragma unroll
        for (int j = 0; j < PC; j++) { sum += vals[r][j]; sq += vals[r][j] * vals[r][j]; }
        #pragma unroll
        for (int o = 16; o > 0; o >>= 1) {
            sum += __shfl_xor_sync(0xffffffffu, sum, o);
            sq  += __shfl_xor_sync(0xffffffffu, sq,  o);
        }
        const float mu  = sum * (1.0f / COUT);
        const float var = fmaxf(sq * (1.0f / COUT) - mu * mu, 0.f);
        const float inv = rsqrtf(var + 1e-5f);
        float v[PC];
        #pragma unroll
        for (int j = 0; j < PC; j++) {
            v[j] = fmaxf(fmaf(gr[j] * (vals[r][j] - mu), inv, br[j]), 0.f);
            mx[j] = fmaxf(mx[j], v[j]);
        }
        if (!LAST) {
            if constexpr (PC == 4)
                *(float4*)(out_s + (rbase + r) * COUT + lane * 4) =
                    make_float4(v[0], v[1], v[2], v[3]);
            else if constexpr (PC == 2)
                *(float2*)(out_s + (rbase + r) * COUT + lane * 2) =
                    make_float2(v[0], v[1]);
            else
                out_s[(rbase + r) * COUT + lane] = v[0];
        }
    }
    // Per-warp column max -> wmax[warp][*] (no atomics; each warp owns a row)
    if constexpr (PC == 4)
        *(float4*)(wmax + warp * 128 + lane * 4) = make_float4(mx[0], mx[1], mx[2], mx[3]);
    else if constexpr (PC == 2)
        *(float2*)(wmax + warp * 128 + lane * 2) = make_float2(mx[0], mx[1]);
    else
        wmax[warp * 128 + lane] = mx[0];
    __syncthreads();
}

__global__ void __launch_bounds__(256, 3) stage1_kernel(
    const float* __restrict__ data,
    const float* __restrict__ W0, const float* __restrict__ b0,
    const float* __restrict__ g0, const float* __restrict__ be0,
    const float* __restrict__ W1, const float* __restrict__ b1,
    const float* __restrict__ g1, const float* __restrict__ be1,
    const float* __restrict__ W2, const float* __restrict__ b2,
    const float* __restrict__ g2, const float* __restrict__ be2)
{
    extern __shared__ float smem[];
    // Layout (18816 floats = 73.5 KB; 3 CTAs/SM = 220.5 KB <= 228 KB):
    float* W0s  = smem;                  // 32*32   = 1024
    float* W1s  = W0s + 1024;            // 32*64   = 2048
    float* W2s  = W1s + 2048;            // 64*128  = 8192
    float* bufA = W2s + 8192;            // 64*64 (x 64x32, later h1 64x64)
    float* bufB = bufA + 4096;           // 64*32 (h0)
    float* wmax = bufB + 2048;           // 8*128 per-warp col maxes
    float* aggp = wmax + 1024;           // 128
    float* shsP = aggp + 128;            // 256 partial shared terms

    const int tid = threadIdx.x;
    const int blk = blockIdx.x;          // b*NPOLY + p
    const int b = blk >> 8, p = blk & 255;

    // Stage ALL layer weights once (independent LDG.128s, high MLP),
    // overlapped with the x-tile load below. W_top rows are the first
    // CIN*COUT floats of each weight matrix (contiguous).
    ((float4*)W0s)[tid] = ((const float4*)W0)[tid];                    // 256 f4
    ((float4*)W1s)[tid] = ((const float4*)W1)[tid];                    // 512 f4
    ((float4*)W1s)[tid + 256] = ((const float4*)W1)[tid + 256];
    #pragma unroll
    for (int i = 0; i < 8; i++)                                        // 2048 f4
        ((float4*)W2s)[tid + i * 256] = ((const float4*)W2)[tid + i * 256];

    // Load x tile (64 x 32), zero channel 31 (vecs[:, :, -1] = 0)
    const float* src = data + (size_t)b * V_TOT * LDIM + LDIM + (size_t)p * VPP * LDIM;
    for (int i = tid; i < 64 * 32; i += 256) {
        float v = src[i];
        if ((i & 31) == 31) v = 0.f;
        bufA[i] = v;
    }
    __syncthreads();

    layer<32, 32,  true,  false, 32>(bufA, bufB, W0s, W0, b0, g0, be0, aggp, shsP, wmax, tid);
    layer<32, 64,  false, false, 32>(bufB, bufA, W1s, W1, b1, g1, be1, aggp, shsP, wmax, tid);
    layer<64, 128, false, true,  64>(bufA, nullptr, W2s, W2, b2, g2, be2, aggp, shsP, wmax, tid);

    // Final reduction of layer-3 per-warp maxes -> P2
    if (tid < 128) {
        float m = wmax[tid];
        #pragma unroll
        for (int w = 1; w < 8; w++) m = fmaxf(m, wmax[w * 128 + tid]);
        g_P2[(size_t)blk * 128 + tid] = m;
    }
}

// ---------------------------------------------------------------------------
// Fold Wq/Wk/Wv:  W_eff[j][c] = W[j][c] + W[j+128][c]   (P = [agg2, agg2]).
// Runs with high parallelism; leaves folded weights hot in L2 for attn.
// ---------------------------------------------------------------------------
__global__ void __launch_bounds__(256) fold_kernel(
    const float* __restrict__ Wq, const float* __restrict__ Wk,
    const float* __restrict__ Wv)
{
    const int i = blockIdx.x * 256 + threadIdx.x;
    if (i >= 128 * 256) return;
    const int j = i >> 8, c = i & 255;
    g_Wq[i] = Wq[j * 256 + c] + Wq[(j + 128) * 256 + c];
    g_Wk[i] = Wk[j * 256 + c] + Wk[(j + 128) * 256 + c];
    g_Wv[i] = Wv[j * 256 + c] + Wv[(j + 128) * 256 + c];
}

// ---------------------------------------------------------------------------
// Stage 2: attention, algebraically reduced. One block per batch.
//   q = P2[b, aid] @ Wq_eff + bq
//   t = Wk_eff @ q            (scores = P2 . t / 16 + const; const cancels)
//   att = softmax(scores)
//   out = (sum_p att_p * P2[b,p]) @ Wv_eff + bv
// ---------------------------------------------------------------------------
__global__ void __launch_bounds__(256) attn_kernel(
    const float* __restrict__ data,
    const float* __restrict__ bq, const float* __restrict__ bv,
    float* __restrict__ out)
{
    __shared__ float ps[128], qs[256], ts[128], att[256], pbar[128], red[256];
    const int b = blockIdx.x, tid = threadIdx.x;

    const int aid = (int)data[(size_t)b * V_TOT * LDIM];   // data[b][0][0]
    if (tid < 128) ps[tid] = g_P2[((size_t)b * NPOLY + aid) * 128 + tid];
    __syncthreads();

    // q[c] (unroll 8 => 8 outstanding LDGs vs L2 latency)
    {
        float acc = bq[tid];
        #pragma unroll 8
        for (int j = 0; j < 128; j++) acc = fmaf(ps[j], g_Wq[j * 256 + tid], acc);
        qs[tid] = acc;
    }
    __syncthreads();

    // t[j] = sum_c Wk_eff[j][c] * q[c]
    if (tid < 128) {
        float acc = 0.f;
        #pragma unroll 8
        for (int c = 0; c < 256; c++) acc = fmaf(g_Wk[tid * 256 + c], qs[c], acc);
        ts[tid] = acc;
    }
    __syncthreads();

    // scores (per poly p = tid)
    float s = 0.f;
    {
        const float4* Pp = (const float4*)(g_P2 + ((size_t)b * NPOLY + tid) * 128);
        #pragma unroll 8
        for (int j = 0; j < 32; j++) {
            float4 pv = Pp[j];
            s = fmaf(pv.x, ts[4 * j + 0], s);
            s = fmaf(pv.y, ts[4 * j + 1], s);
            s = fmaf(pv.z, ts[4 * j + 2], s);
            s = fmaf(pv.w, ts[4 * j + 3], s);
        }
        s *= 0.0625f;   // 1/sqrt(256)
    }
    // softmax over 256
    red[tid] = s; __syncthreads();
    for (int o = 128; o > 0; o >>= 1) {
        if (tid < o) red[tid] = fmaxf(red[tid], red[tid + o]);
        __syncthreads();
    }
    const float m = red[0]; __syncthreads();
    const float e = expf(s - m);
    red[tid] = e; __syncthreads();
    for (int o = 128; o > 0; o >>= 1) {
        if (tid < o) red[tid] += red[tid + o];
        __syncthreads();
    }
    att[tid] = e / red[0];
    __syncthreads();

    // pbar[j] = sum_p att[p] * P2[b,p,j]   (coalesced across tid=j)
    if (tid < 128) {
        float acc = 0.f;
        const float* Pb = g_P2 + (size_t)b * NPOLY * 128;
        #pragma unroll 8
        for (int p = 0; p < 256; p++) acc = fmaf(att[p], Pb[p * 128 + tid], acc);
        pbar[tid] = acc;
    }
    __syncthreads();

    // out[c]
    {
        float acc = bv[tid];
        #pragma unroll 8
        for (int j = 0; j < 128; j++) acc = fmaf(pbar[j], g_Wv[j * 256 + tid], acc);
        out[b * 256 + tid] = acc;
    }
}

// ---------------------------------------------------------------------------
extern "C" void kernel_launch(void* const* d_in, const int* in_sizes, int n_in,
                              void* d_out, int out_size)
{
    const float* data = (const float*)d_in[0];
    const float* W0 = (const float*)d_in[1];
    const float* b0 = (const float*)d_in[2];
    const float* g0 = (const float*)d_in[3];
    const float* be0= (const float*)d_in[4];
    const float* W1 = (const float*)d_in[5];
    const float* b1 = (const float*)d_in[6];
    const float* g1 = (const float*)d_in[7];
    const float* be1= (const float*)d_in[8];
    const float* W2 = (const float*)d_in[9];
    const float* b2 = (const float*)d_in[10];
    const float* g2 = (const float*)d_in[11];
    const float* be2= (const float*)d_in[12];
    const float* Wq = (const float*)d_in[13];
    const float* bq = (const float*)d_in[14];
    const float* Wk = (const float*)d_in[15];
    const float* bk = (const float*)d_in[16];
    const float* Wv = (const float*)d_in[17];
    const float* bv = (const float*)d_in[18];
    float* out = (float*)d_out;
    (void)bk;

    const int smem_bytes = (1024 + 2048 + 8192 + 4096 + 2048 + 1024 + 128 + 256)
                           * (int)sizeof(float);   // 75264 B
    cudaFuncSetAttribute(stage1_kernel,
                         cudaFuncAttributeMaxDynamicSharedMemorySize, smem_bytes);

    stage1_kernel<<<NB * NPOLY, 256, smem_bytes>>>(
        data, W0, b0, g0, be0, W1, b1, g1, be1, W2, b2, g2, be2);
    fold_kernel<<<(128 * 256 + 255) / 256, 256>>>(Wq, Wk, Wv);
    attn_kernel<<<NB, 256>>>(data, bq, bv, out);
}

// round 17
// speedup vs baseline: 1.9961x; 1.2302x over previous
#include <cuda_runtime.h>
#include <cuda_bf16.h>
#include <math.h>
#include <stdint.h>

// Problem constants
#define NB     32
#define NPOLY  256
#define VPP    64
#define LDIM   32
#define V_TOT  (1 + NPOLY * VPP)

// Scratch (device globals: no allocations allowed)
__device__ float g_P2[NB * NPOLY * 128];
__device__ float g_Wq[128 * 256];
__device__ float g_Wk[128 * 256];
__device__ float g_Wv[128 * 256];
// W2-top transposed to [n][k] bf16 hi/lo (plain row-major, k contiguous)
__device__ __align__(16) unsigned short g_W2hi[128 * 64];
__device__ __align__(16) unsigned short g_W2lo[128 * 64];

// ---- packed f32x2 helpers ------------------------------------------------
__device__ __forceinline__ unsigned long long pack2(float x, float y) {
    unsigned long long r;
    asm("mov.b64 %0, {%1, %2};" : "=l"(r) : "f"(x), "f"(y));
    return r;
}
__device__ __forceinline__ unsigned long long ffma2(unsigned long long a,
                                                    unsigned long long b,
                                                    unsigned long long c) {
    unsigned long long d;
    asm("fma.rn.f32x2 %0, %1, %2, %3;" : "=l"(d) : "l"(a), "l"(b), "l"(c));
    return d;
}
__device__ __forceinline__ float2 unpack2(unsigned long long v) {
    float2 f;
    asm("mov.b64 {%0, %1}, %2;" : "=f"(f.x), "=f"(f.y) : "l"(v));
    return f;
}

// ---- smem layout (u32 units) ----------------------------------------------
// A/B tiles: [128 rows][36 u32] (32 used = 64 bf16, 4 pad) -> conflict-free
// fragment LDS: bank = (36*g + t) mod 32.
#define TSTR    36
#define O_AHI   0
#define O_ALO   4608
#define O_BHI   9216
#define O_BLO   13824
#define O_BUFA  18432   // 2048 f32 : x tile (64x32)
#define O_BUFB  20480   // 2048 f32 : h0 (64x32)
#define O_W0    22528   // 1024 f32 : W0 top
#define O_W1    23552   // 2048 f32 : W1 top
#define O_WMAX  25600   // 1024 f32 : 8x128 per-warp col maxes
#define O_AGG1  26624   // 32 f32
#define O_AGG2  26656   // 128 f32 (2x64)
#define O_SHS   26784   // 256 f32 (layer2 partials / layer3 shared terms)
#define O_GB    27040   // 256 f32 (g2, be2)
#define SMEM_U32 27296
#define SMEM_BYTES (SMEM_U32 * 4)

// ---------------------------------------------------------------------------
// Layer 1: 64x32 @ W0top(32x32) + LN + ReLU -> bufB; per-warp col max.
// ---------------------------------------------------------------------------
__device__ __forceinline__ void layer1_fn(
    const float* __restrict__ bufA, float* __restrict__ bufB,
    const float* __restrict__ W0s, const float* __restrict__ b0,
    const float* __restrict__ g0, const float* __restrict__ be0,
    float* __restrict__ wmax, int tid)
{
    const int warp = tid >> 5, lane = tid & 31, rbase = warp * 8;
    const float gr = g0[lane], br = be0[lane];
    float mx = 0.f;
    float acc[8];
    {
        const float s0 = b0[lane];
        #pragma unroll
        for (int r = 0; r < 8; r++) acc[r] = s0;
    }
    for (int k0 = 0; k0 < 32; k0 += 4) {
        const float w0 = W0s[(k0 + 0) * 32 + lane];
        const float w1 = W0s[(k0 + 1) * 32 + lane];
        const float w2 = W0s[(k0 + 2) * 32 + lane];
        const float w3 = W0s[(k0 + 3) * 32 + lane];
        #pragma unroll
        for (int r = 0; r < 8; r++) {
            const float4 a = *(const float4*)(bufA + (rbase + r) * 32 + k0);
            acc[r] = fmaf(a.x, w0, acc[r]);
            acc[r] = fmaf(a.y, w1, acc[r]);
            acc[r] = fmaf(a.z, w2, acc[r]);
            acc[r] = fmaf(a.w, w3, acc[r]);
        }
    }
    #pragma unroll
    for (int r = 0; r < 8; r++) {
        float sum = acc[r], sq = acc[r] * acc[r];
        #pragma unroll
        for (int o = 16; o > 0; o >>= 1) {
            sum += __shfl_xor_sync(0xffffffffu, sum, o);
            sq  += __shfl_xor_sync(0xffffffffu, sq,  o);
        }
        const float mu  = sum * (1.0f / 32.f);
        const float var = fmaxf(sq * (1.0f / 32.f) - mu * mu, 0.f);
        const float inv = rsqrtf(var + 1e-5f);
        const float v = fmaxf(fmaf(gr * (acc[r] - mu), inv, br), 0.f);
        bufB[(rbase + r) * 32 + lane] = v;
        mx = fmaxf(mx, v);
    }
    wmax[warp * 128 + lane] = mx;
    __syncthreads();
}

// ---------------------------------------------------------------------------
// Layer 2: 64x32 @ W1top(32x64) + shared(agg1) + LN + ReLU.
// Output written bf16 hi/lo into padded row-major A tiles (rows pol*64..).
// ---------------------------------------------------------------------------
__device__ __forceinline__ void layer2_fn(
    const float* __restrict__ bufB,
    uint32_t* __restrict__ Ahi, uint32_t* __restrict__ Alo,
    const float* __restrict__ W1s, const float* __restrict__ W1g,
    const float* __restrict__ b1, const float* __restrict__ g1,
    const float* __restrict__ be1, const float* __restrict__ agg1,
    float* __restrict__ shsP, float* __restrict__ wmax, int tid, int pol)
{
    const int warp = tid >> 5, lane = tid & 31, rbase = warp * 8;
    // shared-term partials: 64 cols x split 4 (8 k each)
    {
        const int c = tid & 63, part = tid >> 6;
        float s = (part == 0) ? b1[c] : 0.f;
        const float* wb = W1g + (size_t)(32 + part * 8) * 64 + c;
        const float* ap = agg1 + part * 8;
        #pragma unroll
        for (int kk = 0; kk < 8; kk++) s = fmaf(ap[kk], wb[(size_t)kk * 64], s);
        shsP[part * 64 + c] = s;
    }
    __syncthreads();
    float s0a, s0b;
    {
        const int c0 = lane * 2;
        s0a = shsP[c0]   + shsP[64 + c0]   + shsP[128 + c0]   + shsP[192 + c0];
        s0b = shsP[c0+1] + shsP[64 + c0+1] + shsP[128 + c0+1] + shsP[192 + c0+1];
    }
    const float gr0 = g1[lane*2], gr1 = g1[lane*2+1];
    const float br0 = be1[lane*2], br1 = be1[lane*2+1];
    float mx0 = 0.f, mx1 = 0.f;
    unsigned long long acc[8];
    {
        const unsigned long long i0 = pack2(s0a, s0b);
        #pragma unroll
        for (int r = 0; r < 8; r++) acc[r] = i0;
    }
    for (int k0 = 0; k0 < 32; k0 += 4) {
        unsigned long long w[4];
        #pragma unroll
        for (int kk = 0; kk < 4; kk++)
            w[kk] = *(const unsigned long long*)(W1s + (k0 + kk) * 64 + lane * 2);
        #pragma unroll
        for (int r = 0; r < 8; r++) {
            const float4 a = *(const float4*)(bufB + (rbase + r) * 32 + k0);
            acc[r] = ffma2(pack2(a.x, a.x), w[0], acc[r]);
            acc[r] = ffma2(pack2(a.y, a.y), w[1], acc[r]);
            acc[r] = ffma2(pack2(a.z, a.z), w[2], acc[r]);
            acc[r] = ffma2(pack2(a.w, a.w), w[3], acc[r]);
        }
    }
    #pragma unroll
    for (int r = 0; r < 8; r++) {
        const float2 f = unpack2(acc[r]);
        float sum = f.x + f.y, sq = f.x * f.x + f.y * f.y;
        #pragma unroll
        for (int o = 16; o > 0; o >>= 1) {
            sum += __shfl_xor_sync(0xffffffffu, sum, o);
            sq  += __shfl_xor_sync(0xffffffffu, sq,  o);
        }
        const float mu  = sum * (1.0f / 64.f);
        const float var = fmaxf(sq * (1.0f / 64.f) - mu * mu, 0.f);
        const float inv = rsqrtf(var + 1e-5f);
        const float v0 = fmaxf(fmaf(gr0 * (f.x - mu), inv, br0), 0.f);
        const float v1 = fmaxf(fmaf(gr1 * (f.y - mu), inv, br1), 0.f);
        mx0 = fmaxf(mx0, v0); mx1 = fmaxf(mx1, v1);
        // bf16 split (hi + residual lo), 2 k-contiguous channels per u32
        const __nv_bfloat16 h0 = __float2bfloat16(v0), h1 = __float2bfloat16(v1);
        const __nv_bfloat16 l0 = __float2bfloat16(v0 - __bfloat162float(h0));
        const __nv_bfloat16 l1 = __float2bfloat16(v1 - __bfloat162float(h1));
        const uint32_t hw = (uint32_t)__bfloat16_as_ushort(h0)
                          | ((uint32_t)__bfloat16_as_ushort(h1) << 16);
        const uint32_t lw = (uint32_t)__bfloat16_as_ushort(l0)
                          | ((uint32_t)__bfloat16_as_ushort(l1) << 16);
        const int row = pol * 64 + rbase + r;
        Ahi[row * TSTR + lane] = hw;
        Alo[row * TSTR + lane] = lw;
    }
    wmax[warp * 128 + lane * 2]     = mx0;
    wmax[warp * 128 + lane * 2 + 1] = mx1;
    __syncthreads();
}

// ---------------------------------------------------------------------------
// Stage 1: 2 polys/CTA. Layers 1-2 scalar; layer 3 = warp-level bf16-split
// mma.sync (D = Ahi*Bhi + Ahi*Blo + Alo*Bhi, fp32 accumulators in registers).
// ---------------------------------------------------------------------------
__global__ void __launch_bounds__(256, 2) stage1_kernel(
    const float* __restrict__ data,
    const float* __restrict__ W0, const float* __restrict__ b0,
    const float* __restrict__ g0, const float* __restrict__ be0,
    const float* __restrict__ W1, const float* __restrict__ b1,
    const float* __restrict__ g1, const float* __restrict__ be1,
    const float* __restrict__ W2, const float* __restrict__ b2,
    const float* __restrict__ g2, const float* __restrict__ be2)
{
    extern __shared__ uint32_t sm[];
    uint32_t* Ahi = sm + O_AHI;
    uint32_t* Alo = sm + O_ALO;
    uint32_t* Bhi = sm + O_BHI;
    uint32_t* Blo = sm + O_BLO;
    float* bufA = (float*)(sm + O_BUFA);
    float* bufB = (float*)(sm + O_BUFB);
    float* W0s  = (float*)(sm + O_W0);
    float* W1s  = (float*)(sm + O_W1);
    float* wmax = (float*)(sm + O_WMAX);
    float* agg1 = (float*)(sm + O_AGG1);
    float* agg2 = (float*)(sm + O_AGG2);
    float* shs  = (float*)(sm + O_SHS);
    float* gbs  = (float*)(sm + O_GB);

    const int tid = threadIdx.x;
    const int wid = tid >> 5, lane = tid & 31;
    const int blk = blockIdx.x;                 // b*128 + poly-pair
    const int b = blk >> 7, pp = blk & 127;

    // Stage fp32 weight tops, B tiles (bf16 hi/lo, padded rows), LN params
    ((float4*)W0s)[tid] = ((const float4*)W0)[tid];
    ((float4*)W1s)[tid] = ((const float4*)W1)[tid];
    ((float4*)W1s)[tid + 256] = ((const float4*)W1)[tid + 256];
    {
        const uint4* sh = (const uint4*)g_W2hi;   // [n][k]: 8 uint4 per row
        const uint4* sl = (const uint4*)g_W2lo;
        #pragma unroll
        for (int i = tid; i < 1024; i += 256) {
            const int row = i >> 3, q = i & 7;
            *(uint4*)(Bhi + row * TSTR + q * 4) = sh[i];
            *(uint4*)(Blo + row * TSTR + q * 4) = sl[i];
        }
    }
    gbs[tid] = (tid < 128) ? g2[tid] : be2[tid - 128];

    // Layers 1-2, one poly per pass
    #pragma unroll 1
    for (int pol = 0; pol < 2; pol++) {
        const float* src = data + (size_t)b * V_TOT * LDIM + LDIM
                         + ((size_t)(pp * 2 + pol)) * VPP * LDIM;
        __syncthreads();
        for (int i = tid; i < 2048; i += 256) {
            float v = src[i];
            if ((i & 31) == 31) v = 0.f;
            bufA[i] = v;
        }
        __syncthreads();
        layer1_fn(bufA, bufB, W0s, b0, g0, be0, wmax, tid);
        if (tid < 32) {
            float m = wmax[tid];
            #pragma unroll
            for (int w = 1; w < 8; w++) m = fmaxf(m, wmax[w * 128 + tid]);
            agg1[tid] = m;
        }
        __syncthreads();
        layer2_fn(bufB, Ahi, Alo, W1s, W1, b1, g1, be1, agg1, shs, wmax, tid, pol);
        if (tid < 64) {
            float m = wmax[tid];
            #pragma unroll
            for (int w = 1; w < 8; w++) m = fmaxf(m, wmax[w * 128 + tid]);
            agg2[pol * 64 + tid] = m;
        }
    }
    __syncthreads();

    // Layer-3 shared terms: 2 polys x 128 cols (fp32, from global W2 bottom)
    {
        const int pol = tid >> 7, c = tid & 127;
        const float* wb = W2 + (size_t)64 * 128 + c;
        const float* ag = agg2 + pol * 64;
        float s = b2[c];
        #pragma unroll 8
        for (int k = 0; k < 64; k++) s = fmaf(ag[k], wb[(size_t)k * 128], s);
        shs[tid] = s;
    }
    __syncthreads();

    // Warp MMA: warp wid owns rows rw..rw+15 (poly = wid>>2), all 128 cols.
    const int g = lane >> 2, t = lane & 3;
    const int rw = wid * 16;
    float acc[16][4];
    #pragma unroll
    for (int nt = 0; nt < 16; nt++)
        #pragma unroll
        for (int j = 0; j < 4; j++) acc[nt][j] = 0.f;

    #pragma unroll 1
    for (int prod = 0; prod < 3; prod++) {
        const uint32_t* Ab = (prod == 2) ? Alo : Ahi;
        const uint32_t* Bb = (prod == 1) ? Blo : Bhi;
        #pragma unroll
        for (int ks = 0; ks < 4; ks++) {
            const int kc = ks * 8 + t;
            const uint32_t a0 = Ab[(rw + g)     * TSTR + kc];
            const uint32_t a1 = Ab[(rw + g + 8) * TSTR + kc];
            const uint32_t a2 = Ab[(rw + g)     * TSTR + kc + 4];
            const uint32_t a3 = Ab[(rw + g + 8) * TSTR + kc + 4];
            #pragma unroll
            for (int nt = 0; nt < 16; nt++) {
                const uint32_t b0v = Bb[(nt * 8 + g) * TSTR + kc];
                const uint32_t b1v = Bb[(nt * 8 + g) * TSTR + kc + 4];
                asm volatile(
                    "mma.sync.aligned.m16n8k16.row.col.f32.bf16.bf16.f32 "
                    "{%0,%1,%2,%3}, {%4,%5,%6,%7}, {%8,%9}, {%0,%1,%2,%3};"
                    : "+f"(acc[nt][0]), "+f"(acc[nt][1]),
                      "+f"(acc[nt][2]), "+f"(acc[nt][3])
                    : "r"(a0), "r"(a1), "r"(a2), "r"(a3), "r"(b0v), "r"(b1v));
            }
        }
    }

    // Epilogue: lane holds rows rw+g (acc[.][0..1]) and rw+g+8 (acc[.][2..3]),
    // cols nt*8 + t*2 + {0,1}. LN per row (quad shuffle), ReLU, col max.
    {
        const int pol = wid >> 2;
        const float* s0p = shs + pol * 128;
        float sum0 = 0.f, sq0 = 0.f, sum1 = 0.f, sq1 = 0.f;
        #pragma unroll
        for (int nt = 0; nt < 16; nt++) {
            const int c0 = nt * 8 + t * 2;
            const float x0 = acc[nt][0] + s0p[c0];
            const float x1 = acc[nt][1] + s0p[c0 + 1];
            const float x2 = acc[nt][2] + s0p[c0];
            const float x3 = acc[nt][3] + s0p[c0 + 1];
            acc[nt][0] = x0; acc[nt][1] = x1; acc[nt][2] = x2; acc[nt][3] = x3;
            sum0 += x0 + x1; sq0 += x0 * x0 + x1 * x1;
            sum1 += x2 + x3; sq1 += x2 * x2 + x3 * x3;
        }
        #pragma unroll
        for (int o = 1; o <= 2; o <<= 1) {
            sum0 += __shfl_xor_sync(0xffffffffu, sum0, o);
            sq0  += __shfl_xor_sync(0xffffffffu, sq0,  o);
            sum1 += __shfl_xor_sync(0xffffffffu, sum1, o);
            sq1  += __shfl_xor_sync(0xffffffffu, sq1,  o);
        }
        const float mu0  = sum0 * (1.0f / 128.f);
        const float var0 = fmaxf(sq0 * (1.0f / 128.f) - mu0 * mu0, 0.f);
        const float inv0 = rsqrtf(var0 + 1e-5f);
        const float mu1  = sum1 * (1.0f / 128.f);
        const float var1 = fmaxf(sq1 * (1.0f / 128.f) - mu1 * mu1, 0.f);
        const float inv1 = rsqrtf(var1 + 1e-5f);
        #pragma unroll
        for (int nt = 0; nt < 16; nt++) {
            const int c0 = nt * 8 + t * 2;
            const float ga = gbs[c0],     ba = gbs[128 + c0];
            const float gb2 = gbs[c0 + 1], bb2 = gbs[128 + c0 + 1];
            const float v0 = fmaxf(fmaf(ga  * (acc[nt][0] - mu0), inv0, ba),  0.f);
            const float v1 = fmaxf(fmaf(gb2 * (acc[nt][1] - mu0), inv0, bb2), 0.f);
            const float v2 = fmaxf(fmaf(ga  * (acc[nt][2] - mu1), inv1, ba),  0.f);
            const float v3 = fmaxf(fmaf(gb2 * (acc[nt][3] - mu1), inv1, bb2), 0.f);
            float m0 = fmaxf(v0, v2), m1 = fmaxf(v1, v3);
            #pragma unroll
            for (int o = 4; o <= 16; o <<= 1) {
                m0 = fmaxf(m0, __shfl_xor_sync(0xffffffffu, m0, o));
                m1 = fmaxf(m1, __shfl_xor_sync(0xffffffffu, m1, o));
            }
            if (g == 0) {
                wmax[wid * 128 + c0]     = m0;
                wmax[wid * 128 + c0 + 1] = m1;
            }
        }
    }
    __syncthreads();

    // Final per-poly column max over that poly's 4 warps -> P2
    {
        const int pol = tid >> 7, c = tid & 127;
        float m = wmax[(pol * 4) * 128 + c];
        #pragma unroll
        for (int w = 1; w < 4; w++)
            m = fmaxf(m, wmax[(pol * 4 + w) * 128 + c]);
        g_P2[((size_t)b * NPOLY + (pp * 2 + pol)) * 128 + c] = m;
    }
}

// ---------------------------------------------------------------------------
// Prep: fold Wq/Wk/Wv; build W2top^T bf16 hi/lo ([n][k] plain row-major).
// ---------------------------------------------------------------------------
__global__ void __launch_bounds__(256) fold_kernel(
    const float* __restrict__ Wq, const float* __restrict__ Wk,
    const float* __restrict__ Wv, const float* __restrict__ W2)
{
    const int i = blockIdx.x * 256 + threadIdx.x;
    if (i >= 128 * 256) return;
    const int j = i >> 8, c = i & 255;
    g_Wq[i] = Wq[j * 256 + c] + Wq[(j + 128) * 256 + c];
    g_Wk[i] = Wk[j * 256 + c] + Wk[(j + 128) * 256 + c];
    g_Wv[i] = Wv[j * 256 + c] + Wv[(j + 128) * 256 + c];
    if (i < 128 * 64) {
        const int n = i >> 6, k = i & 63;
        const float v = W2[(size_t)k * 128 + n];   // B[n][k] = W2top[k][n]
        const __nv_bfloat16 hi = __float2bfloat16(v);
        const __nv_bfloat16 lo = __float2bfloat16(v - __bfloat162float(hi));
        g_W2hi[i] = __bfloat16_as_ushort(hi);
        g_W2lo[i] = __bfloat16_as_ushort(lo);
    }
}

// ---------------------------------------------------------------------------
// Stage 2: attention (algebraically reduced). One block per batch.
// ---------------------------------------------------------------------------
__global__ void __launch_bounds__(256) attn_kernel(
    const float* __restrict__ data,
    const float* __restrict__ bq, const float* __restrict__ bv,
    float* __restrict__ out)
{
    __shared__ float ps[128], qs[256], ts[128], att[256], pbar[128], red[256];
    const int b = blockIdx.x, tid = threadIdx.x;

    const int aid = (int)data[(size_t)b * V_TOT * LDIM];
    if (tid < 128) ps[tid] = g_P2[((size_t)b * NPOLY + aid) * 128 + tid];
    __syncthreads();

    {
        float acc = bq[tid];
        #pragma unroll 8
        for (int j = 0; j < 128; j++) acc = fmaf(ps[j], g_Wq[j * 256 + tid], acc);
        qs[tid] = acc;
    }
    __syncthreads();

    if (tid < 128) {
        float acc = 0.f;
        #pragma unroll 8
        for (int c = 0; c < 256; c++) acc = fmaf(g_Wk[tid * 256 + c], qs[c], acc);
        ts[tid] = acc;
    }
    __syncthreads();

    float s = 0.f;
    {
        const float4* Pp = (const float4*)(g_P2 + ((size_t)b * NPOLY + tid) * 128);
        #pragma unroll 8
        for (int j = 0; j < 32; j++) {
            float4 pv = Pp[j];
            s = fmaf(pv.x, ts[4 * j + 0], s);
            s = fmaf(pv.y, ts[4 * j + 1], s);
            s = fmaf(pv.z, ts[4 * j + 2], s);
            s = fmaf(pv.w, ts[4 * j + 3], s);
        }
        s *= 0.0625f;
    }
    red[tid] = s; __syncthreads();
    for (int o = 128; o > 0; o >>= 1) {
        if (tid < o) red[tid] = fmaxf(red[tid], red[tid + o]);
        __syncthreads();
    }
    const float m = red[0]; __syncthreads();
    const float e = expf(s - m);
    red[tid] = e; __syncthreads();
    for (int o = 128; o > 0; o >>= 1) {
        if (tid < o) red[tid] += red[tid + o];
        __syncthreads();
    }
    att[tid] = e / red[0];
    __syncthreads();

    if (tid < 128) {
        float acc = 0.f;
        const float* Pb = g_P2 + (size_t)b * NPOLY * 128;
        #pragma unroll 8
        for (int p = 0; p < 256; p++) acc = fmaf(att[p], Pb[p * 128 + tid], acc);
        pbar[tid] = acc;
    }
    __syncthreads();

    {
        float acc = bv[tid];
        #pragma unroll 8
        for (int j = 0; j < 128; j++) acc = fmaf(pbar[j], g_Wv[j * 256 + tid], acc);
        out[b * 256 + tid] = acc;
    }
}

// ---------------------------------------------------------------------------
extern "C" void kernel_launch(void* const* d_in, const int* in_sizes, int n_in,
                              void* d_out, int out_size)
{
    const float* data = (const float*)d_in[0];
    const float* W0 = (const float*)d_in[1];
    const float* b0 = (const float*)d_in[2];
    const float* g0 = (const float*)d_in[3];
    const float* be0= (const float*)d_in[4];
    const float* W1 = (const float*)d_in[5];
    const float* b1 = (const float*)d_in[6];
    const float* g1 = (const float*)d_in[7];
    const float* be1= (const float*)d_in[8];
    const float* W2 = (const float*)d_in[9];
    const float* b2 = (const float*)d_in[10];
    const float* g2 = (const float*)d_in[11];
    const float* be2= (const float*)d_in[12];
    const float* Wq = (const float*)d_in[13];
    const float* bq = (const float*)d_in[14];
    const float* Wk = (const float*)d_in[15];
    const float* bk = (const float*)d_in[16];
    const float* Wv = (const float*)d_in[17];
    const float* bv = (const float*)d_in[18];
    float* out = (float*)d_out;
    (void)bk;

    cudaFuncSetAttribute(stage1_kernel,
                         cudaFuncAttributeMaxDynamicSharedMemorySize, SMEM_BYTES);

    // Prep must precede stage1 (stage1 reads g_W2hi/g_W2lo)
    fold_kernel<<<(128 * 256 + 255) / 256, 256>>>(Wq, Wk, Wv, W2);
    stage1_kernel<<<NB * NPOLY / 2, 256, SMEM_BYTES>>>(
        data, W0, b0, g0, be0, W1, b1, g1, be1, W2, b2, g2, be2);
    attn_kernel<<<NB, 256>>>(data, bq, bv, out);
}